// round 8
// baseline (speedup 1.0000x reference)
#include <cuda_runtime.h>
#include <cuda_fp16.h>

#define NN 100000   // nodes
#define EE 500000   // edges
#define ND 16       // node_dim
#define ED 8        // edge_dim
#define HD 16       // hidden_dim
#define NG 32       // graphs

// Scratch (no allocation allowed -> __device__ globals)
__device__ __align__(128) __half g_v[(size_t)NN * HD * ED];  // 25.6 MB: v[n][o][d] fp16
__device__ __align__(128) float g_bb[(size_t)NN * HD];
__device__ __align__(128) float g_agg1[(size_t)NN * HD];
__device__ __align__(128) float g_agg2[(size_t)NN * HD];
__device__ float g_sums[NG * HD];
__device__ float g_cnts[NG];

// ---------------------------------------------------------------------------
// Prep v5: 64 nodes/block, 256 threads. Thread (ng=tid>>4, o=tid&15)
// computes, for 4 nodes n = base+ng*4+j:
//   v[n][o][d] = sum_i h[n][i] * W[d*256 + i*16 + o]    (fp16, packed half8)
//   bb[n][o]   = sum_i h[n][i] * b[i*16 + o]
//   agg[n][o]  = bias[o] + sum_i h[n][i] * root[i*16 + o]
// W staged transposed in smem as sWt[i][o][d] so each thread reads its 8
// d-values with 2 conflict-free LDS.128 per i.
// ---------------------------------------------------------------------------
template <bool RELU_IN, bool ZERO_POOL>
__global__ void __launch_bounds__(256) prep_kernel(
    const float* __restrict__ h, const float* __restrict__ W,
    const float* __restrict__ b, const float* __restrict__ root,
    const float* __restrict__ bias,
    __half* __restrict__ v, float* __restrict__ bb, float* __restrict__ agg)
{
    __shared__ float sWt[ND * HD * ED];   // 8 KB, [i][o][d]
    __shared__ float sR[ND * HD];
    __shared__ float sB[ND * HD];
    __shared__ float sBias[HD];
    __shared__ float sH[64 * 16];         // 4 KB

    int tid = threadIdx.x;
    if (ZERO_POOL && blockIdx.x == 0) {
        for (int i = tid; i < NG * HD; i += 256) g_sums[i] = 0.f;
        if (tid < NG) g_cnts[tid] = 0.f;
    }
    // transpose W[d][i][o] -> sWt[i][o][d]
    for (int idx = tid; idx < 2048; idx += 256) {
        int d = idx >> 8;
        int io = idx & 255;               // i*16 + o
        sWt[io * 8 + d] = __ldg(W + idx);
    }
    for (int i = tid; i < 256; i += 256) { sR[i] = root[i]; sB[i] = b[i]; }
    if (tid < HD) sBias[tid] = bias[tid];

    int nodeBase = blockIdx.x * 64;
    {
        int node = nodeBase + (tid >> 2);
        float4 hv = make_float4(0.f, 0.f, 0.f, 0.f);
        if (node < NN)
            hv = __ldg(reinterpret_cast<const float4*>(h) + (size_t)node * 4 + (tid & 3));
        if (RELU_IN) {
            hv.x = fmaxf(hv.x, 0.f); hv.y = fmaxf(hv.y, 0.f);
            hv.z = fmaxf(hv.z, 0.f); hv.w = fmaxf(hv.w, 0.f);
        }
        reinterpret_cast<float4*>(sH)[tid] = hv;
    }
    __syncthreads();

    int o = tid & 15;
    int ng = tid >> 4;   // 0..15, owns nodes nodeBase + ng*4 + j

    float vr[4][8];
    float bbv[4], rt[4];
#pragma unroll
    for (int j = 0; j < 4; j++) {
        bbv[j] = 0.f; rt[j] = sBias[o];
#pragma unroll
        for (int d = 0; d < 8; d++) vr[j][d] = 0.f;
    }

#pragma unroll
    for (int i = 0; i < 16; i++) {
        const float4* w4 = reinterpret_cast<const float4*>(sWt + (i * 16 + o) * 8);
        float4 w0 = w4[0], w1 = w4[1];
        float rw = sR[i * 16 + o];
        float bw = sB[i * 16 + o];
#pragma unroll
        for (int j = 0; j < 4; j++) {
            float hv = sH[(ng * 4 + j) * 16 + i];   // warp-broadcast
            vr[j][0] = fmaf(hv, w0.x, vr[j][0]);
            vr[j][1] = fmaf(hv, w0.y, vr[j][1]);
            vr[j][2] = fmaf(hv, w0.z, vr[j][2]);
            vr[j][3] = fmaf(hv, w0.w, vr[j][3]);
            vr[j][4] = fmaf(hv, w1.x, vr[j][4]);
            vr[j][5] = fmaf(hv, w1.y, vr[j][5]);
            vr[j][6] = fmaf(hv, w1.z, vr[j][6]);
            vr[j][7] = fmaf(hv, w1.w, vr[j][7]);
            rt[j]  = fmaf(hv, rw, rt[j]);
            bbv[j] = fmaf(hv, bw, bbv[j]);
        }
    }

#pragma unroll
    for (int j = 0; j < 4; j++) {
        int node = nodeBase + ng * 4 + j;
        if (node < NN) {
            union { uint4 u; __half2 h2[4]; } pk;
            pk.h2[0] = __floats2half2_rn(vr[j][0], vr[j][1]);
            pk.h2[1] = __floats2half2_rn(vr[j][2], vr[j][3]);
            pk.h2[2] = __floats2half2_rn(vr[j][4], vr[j][5]);
            pk.h2[3] = __floats2half2_rn(vr[j][6], vr[j][7]);
            reinterpret_cast<uint4*>(v)[(size_t)node * 16 + o] = pk.u;
            agg[(size_t)node * 16 + o] = rt[j];
            bb[(size_t)node * 16 + o] = bbv[j];
        }
    }
}

// ---------------------------------------------------------------------------
// Edge kernel v5: 16 lanes per edge, lane o handles output o.
// One LDG.128 grabs all 8 fp16 v[src][o][d]; 16 lanes cover the node's
// 256B (2 lines) fully coalesced. ea/bb fp32; scalar red.global.add.f32.
// ---------------------------------------------------------------------------
__global__ void __launch_bounds__(256) edge_kernel(
    const int* __restrict__ ei, const float* __restrict__ ea,
    const __half* __restrict__ v, const float* __restrict__ bb,
    float* __restrict__ agg)
{
    int gid = blockIdx.x * 256 + threadIdx.x;
    int e = gid >> 4;
    if (e >= EE) return;
    int o = gid & 15;

    int src = __ldg(ei + e);
    int dst = __ldg(ei + EE + e);

    const float4* eap = reinterpret_cast<const float4*>(ea + (size_t)e * 8);
    float4 ea0 = __ldg(eap);        // broadcast across the 16 lanes
    float4 ea1 = __ldg(eap + 1);

    union { uint4 u; __half2 h2[4]; } pk;
    pk.u = __ldg(reinterpret_cast<const uint4*>(v) + (size_t)src * 16 + o);
    float2 f0 = __half22float2(pk.h2[0]);
    float2 f1 = __half22float2(pk.h2[1]);
    float2 f2 = __half22float2(pk.h2[2]);
    float2 f3 = __half22float2(pk.h2[3]);

    float m = __ldg(bb + (size_t)src * 16 + o);
    m = fmaf(ea0.x, f0.x, m); m = fmaf(ea0.y, f0.y, m);
    m = fmaf(ea0.z, f1.x, m); m = fmaf(ea0.w, f1.y, m);
    m = fmaf(ea1.x, f2.x, m); m = fmaf(ea1.y, f2.y, m);
    m = fmaf(ea1.z, f3.x, m); m = fmaf(ea1.w, f3.y, m);

    asm volatile("red.global.add.f32 [%0], %1;"
                 :: "l"(agg + (size_t)dst * 16 + o), "f"(m) : "memory");
}

// ---------------------------------------------------------------------------
// Pooling: batch sorted -> register-accumulate runs, flush on change.
// ---------------------------------------------------------------------------
#define POOL_NODES_PER_HALF 32
__global__ void __launch_bounds__(256) pool_kernel(
    const float* __restrict__ agg, const int* __restrict__ batch)
{
    int gwarp = (blockIdx.x * 256 + threadIdx.x) >> 5;
    int lane = threadIdx.x & 31;
    int o = lane & 15;
    int sub = lane >> 4;
    int base = (gwarp * 2 + sub) * POOL_NODES_PER_HALF;

    float rsum = 0.f, rcnt = 0.f;
    int curg = -1;
#pragma unroll 4
    for (int k = 0; k < POOL_NODES_PER_HALF; k++) {
        int node = base + k;
        if (node >= NN) break;
        int g = __ldg(batch + node);
        if (g != curg) {
            if (curg >= 0) {
                atomicAdd(&g_sums[curg * HD + o], rsum);
                if (o == 0) atomicAdd(&g_cnts[curg], rcnt);
            }
            curg = g; rsum = 0.f; rcnt = 0.f;
        }
        rsum += fmaxf(__ldg(agg + (size_t)node * 16 + o), 0.f);
        rcnt += 1.f;
    }
    if (curg >= 0) {
        atomicAdd(&g_sums[curg * HD + o], rsum);
        if (o == 0) atomicAdd(&g_cnts[curg], rcnt);
    }
}

__global__ void final_kernel(float* __restrict__ out)
{
    int t = threadIdx.x;
    if (t < NG * HD) {
        float c = g_cnts[t >> 4];
        out[t] = g_sums[t] / fmaxf(c, 1.f);
    }
}

// ---------------------------------------------------------------------------
// Launch
// ---------------------------------------------------------------------------
extern "C" void kernel_launch(void* const* d_in, const int* in_sizes, int n_in,
                              void* d_out, int out_size)
{
    const float* x     = (const float*)d_in[0];
    const float* ea    = (const float*)d_in[1];
    const float* W1    = (const float*)d_in[2];
    const float* b1    = (const float*)d_in[3];
    const float* root1 = (const float*)d_in[4];
    const float* bias1 = (const float*)d_in[5];
    const float* W2    = (const float*)d_in[6];
    const float* b2    = (const float*)d_in[7];
    const float* root2 = (const float*)d_in[8];
    const float* bias2 = (const float*)d_in[9];
    const int*   ei    = (const int*)d_in[10];
    const int*   batch = (const int*)d_in[11];
    float* out = (float*)d_out;

    __half* v;
    float *bb, *agg1, *agg2;
    cudaGetSymbolAddress((void**)&v, g_v);
    cudaGetSymbolAddress((void**)&bb, g_bb);
    cudaGetSymbolAddress((void**)&agg1, g_agg1);
    cudaGetSymbolAddress((void**)&agg2, g_agg2);

    const int prep_grid = (NN + 63) / 64;
    const int edge_grid = (EE * 16 + 255) / 256;
    const int pool_halves = (NN + POOL_NODES_PER_HALF - 1) / POOL_NODES_PER_HALF;
    const int pool_grid = (pool_halves / 2 + 7) / 8 + 1;

    prep_kernel<false, true><<<prep_grid, 256>>>(x, W1, b1, root1, bias1, v, bb, agg1);
    edge_kernel<<<edge_grid, 256>>>(ei, ea, v, bb, agg1);
    prep_kernel<true, false><<<prep_grid, 256>>>(agg1, W2, b2, root2, bias2, v, bb, agg2);
    edge_kernel<<<edge_grid, 256>>>(ei, ea, v, bb, agg2);
    pool_kernel<<<pool_grid, 256>>>(agg2, batch);
    final_kernel<<<1, 512>>>(out);
}

// round 9
// speedup vs baseline: 1.1963x; 1.1963x over previous
#include <cuda_runtime.h>
#include <cuda_fp16.h>

#define NN 100000   // nodes
#define EE 500000   // edges
#define ND 16       // node_dim
#define ED 8        // edge_dim
#define HD 16       // hidden_dim
#define NG 32       // graphs

// Scratch (no allocation allowed -> __device__ globals)
// v layout (fp16, 256B/node): uint4 index node*16 + p*8 + r, p=d>>2, r=o>>1;
// within the 16B: halfs [o_even d0..d3 | o_odd d0..d3] for p=0 (d4..d7 for p=1)
__device__ __align__(128) __half g_v[(size_t)NN * HD * ED];
__device__ __align__(128) float g_bb[(size_t)NN * HD];
__device__ __align__(128) float g_agg1[(size_t)NN * HD];
__device__ __align__(128) float g_agg2[(size_t)NN * HD];
__device__ float g_sums[NG * HD];
__device__ float g_cnts[NG];

// ---------------------------------------------------------------------------
// Prep v6: 64 nodes/block, 256 threads. Thread (ng=tid>>4, o=tid&15)
// computes, for 4 nodes n = base+ng*4+j:
//   v[n][o][d] = sum_i h[n][i] * W[d*256 + i*16 + o]  (fp16, pair-interleaved)
//   bb[n][o]   = sum_i h[n][i] * b[i*16 + o]
//   agg[n][o]  = bias[o] + sum_i h[n][i] * root[i*16 + o]
// W staged transposed in smem as sWt[i][o][d] (2 conflict-free LDS.128 per i).
// v written as two STG.64 per (node,o): d0-3 at n*256 + (o>>1)*16 + (o&1)*8,
// d4-7 at +128B. Threads of a half-warp cover contiguous 128B per store.
// ---------------------------------------------------------------------------
template <bool RELU_IN, bool ZERO_POOL>
__global__ void __launch_bounds__(256) prep_kernel(
    const float* __restrict__ h, const float* __restrict__ W,
    const float* __restrict__ b, const float* __restrict__ root,
    const float* __restrict__ bias,
    __half* __restrict__ v, float* __restrict__ bb, float* __restrict__ agg)
{
    __shared__ float sWt[ND * HD * ED];   // 8 KB, [i][o][d]
    __shared__ float sR[ND * HD];
    __shared__ float sB[ND * HD];
    __shared__ float sBias[HD];
    __shared__ float sH[64 * 16];         // 4 KB

    int tid = threadIdx.x;
    if (ZERO_POOL && blockIdx.x == 0) {
        for (int i = tid; i < NG * HD; i += 256) g_sums[i] = 0.f;
        if (tid < NG) g_cnts[tid] = 0.f;
    }
    // transpose W[d][i][o] -> sWt[i][o][d]
    for (int idx = tid; idx < 2048; idx += 256) {
        int d = idx >> 8;
        int io = idx & 255;               // i*16 + o
        sWt[io * 8 + d] = __ldg(W + idx);
    }
    for (int i = tid; i < 256; i += 256) { sR[i] = root[i]; sB[i] = b[i]; }
    if (tid < HD) sBias[tid] = bias[tid];

    int nodeBase = blockIdx.x * 64;
    {
        int node = nodeBase + (tid >> 2);
        float4 hv = make_float4(0.f, 0.f, 0.f, 0.f);
        if (node < NN)
            hv = __ldg(reinterpret_cast<const float4*>(h) + (size_t)node * 4 + (tid & 3));
        if (RELU_IN) {
            hv.x = fmaxf(hv.x, 0.f); hv.y = fmaxf(hv.y, 0.f);
            hv.z = fmaxf(hv.z, 0.f); hv.w = fmaxf(hv.w, 0.f);
        }
        reinterpret_cast<float4*>(sH)[tid] = hv;
    }
    __syncthreads();

    int o = tid & 15;
    int ng = tid >> 4;   // 0..15, owns nodes nodeBase + ng*4 + j

    float vr[4][8];
    float bbv[4], rt[4];
#pragma unroll
    for (int j = 0; j < 4; j++) {
        bbv[j] = 0.f; rt[j] = sBias[o];
#pragma unroll
        for (int d = 0; d < 8; d++) vr[j][d] = 0.f;
    }

#pragma unroll
    for (int i = 0; i < 16; i++) {
        const float4* w4 = reinterpret_cast<const float4*>(sWt + (i * 16 + o) * 8);
        float4 w0 = w4[0], w1 = w4[1];
        float rw = sR[i * 16 + o];
        float bw = sB[i * 16 + o];
#pragma unroll
        for (int j = 0; j < 4; j++) {
            float hv = sH[(ng * 4 + j) * 16 + i];   // warp-broadcast
            vr[j][0] = fmaf(hv, w0.x, vr[j][0]);
            vr[j][1] = fmaf(hv, w0.y, vr[j][1]);
            vr[j][2] = fmaf(hv, w0.z, vr[j][2]);
            vr[j][3] = fmaf(hv, w0.w, vr[j][3]);
            vr[j][4] = fmaf(hv, w1.x, vr[j][4]);
            vr[j][5] = fmaf(hv, w1.y, vr[j][5]);
            vr[j][6] = fmaf(hv, w1.z, vr[j][6]);
            vr[j][7] = fmaf(hv, w1.w, vr[j][7]);
            rt[j]  = fmaf(hv, rw, rt[j]);
            bbv[j] = fmaf(hv, bw, bbv[j]);
        }
    }

    // uint2 units of 8B: node stride = 32; slot = (o>>1)*2 + (o&1); +16 for d4-7
    uint2* v2 = reinterpret_cast<uint2*>(v);
#pragma unroll
    for (int j = 0; j < 4; j++) {
        int node = nodeBase + ng * 4 + j;
        if (node < NN) {
            union { uint2 u; __half2 h2[2]; } lo, hi;
            lo.h2[0] = __floats2half2_rn(vr[j][0], vr[j][1]);
            lo.h2[1] = __floats2half2_rn(vr[j][2], vr[j][3]);
            hi.h2[0] = __floats2half2_rn(vr[j][4], vr[j][5]);
            hi.h2[1] = __floats2half2_rn(vr[j][6], vr[j][7]);
            size_t base = (size_t)node * 32 + (o >> 1) * 2 + (o & 1);
            v2[base] = lo.u;
            v2[base + 16] = hi.u;
            agg[(size_t)node * 16 + o] = rt[j];
            bb[(size_t)node * 16 + o] = bbv[j];
        }
    }
}

// ---------------------------------------------------------------------------
// Edge kernel v6: 8 lanes per edge; lane r owns outputs o=2r, 2r+1.
// Two LDG.128 at node byte offsets r*16 and 128+r*16 (fully coalesced,
// 2 wavefronts/edge) give all 16 halfs. One red.global.add.v2.f32 per lane.
// ---------------------------------------------------------------------------
__global__ void __launch_bounds__(256) edge_kernel(
    const int* __restrict__ ei, const float* __restrict__ ea,
    const __half* __restrict__ v, const float* __restrict__ bb,
    float* __restrict__ agg)
{
    int gid = blockIdx.x * 256 + threadIdx.x;
    int e = gid >> 3;
    if (e >= EE) return;
    int r = gid & 7;

    int src = __ldg(ei + e);
    int dst = __ldg(ei + EE + e);

    const float4* eap = reinterpret_cast<const float4*>(ea + (size_t)e * 8);
    float4 ea0 = __ldg(eap);        // broadcast across 8 lanes
    float4 ea1 = __ldg(eap + 1);

    const uint4* vb = reinterpret_cast<const uint4*>(v) + (size_t)src * 16;
    union { uint4 u; __half2 h2[4]; } l0, l1;
    l0.u = __ldg(vb + r);           // [o_e d0d1 | o_e d2d3 | o_o d0d1 | o_o d2d3]
    l1.u = __ldg(vb + 8 + r);       // same for d4..d7

    float2 bb2 = __ldg(reinterpret_cast<const float2*>(bb + (size_t)src * 16) + r);

    float2 a0 = __half22float2(l0.h2[0]);   // o_e d0,d1
    float2 a1 = __half22float2(l0.h2[1]);   // o_e d2,d3
    float2 a2 = __half22float2(l1.h2[0]);   // o_e d4,d5
    float2 a3 = __half22float2(l1.h2[1]);   // o_e d6,d7
    float2 b0 = __half22float2(l0.h2[2]);   // o_o d0,d1
    float2 b1 = __half22float2(l0.h2[3]);
    float2 b2 = __half22float2(l1.h2[2]);
    float2 b3 = __half22float2(l1.h2[3]);

    float me = bb2.x;
    me = fmaf(ea0.x, a0.x, me); me = fmaf(ea0.y, a0.y, me);
    me = fmaf(ea0.z, a1.x, me); me = fmaf(ea0.w, a1.y, me);
    me = fmaf(ea1.x, a2.x, me); me = fmaf(ea1.y, a2.y, me);
    me = fmaf(ea1.z, a3.x, me); me = fmaf(ea1.w, a3.y, me);

    float mo = bb2.y;
    mo = fmaf(ea0.x, b0.x, mo); mo = fmaf(ea0.y, b0.y, mo);
    mo = fmaf(ea0.z, b1.x, mo); mo = fmaf(ea0.w, b1.y, mo);
    mo = fmaf(ea1.x, b2.x, mo); mo = fmaf(ea1.y, b2.y, mo);
    mo = fmaf(ea1.z, b3.x, mo); mo = fmaf(ea1.w, b3.y, mo);

    asm volatile("red.global.add.v2.f32 [%0], {%1,%2};"
                 :: "l"(agg + (size_t)dst * 16 + r * 2), "f"(me), "f"(mo)
                 : "memory");
}

// ---------------------------------------------------------------------------
// Pooling: batch sorted -> register-accumulate runs, flush on change.
// ---------------------------------------------------------------------------
#define POOL_NODES_PER_HALF 32
__global__ void __launch_bounds__(256) pool_kernel(
    const float* __restrict__ agg, const int* __restrict__ batch)
{
    int gwarp = (blockIdx.x * 256 + threadIdx.x) >> 5;
    int lane = threadIdx.x & 31;
    int o = lane & 15;
    int sub = lane >> 4;
    int base = (gwarp * 2 + sub) * POOL_NODES_PER_HALF;

    float rsum = 0.f, rcnt = 0.f;
    int curg = -1;
#pragma unroll 4
    for (int k = 0; k < POOL_NODES_PER_HALF; k++) {
        int node = base + k;
        if (node >= NN) break;
        int g = __ldg(batch + node);
        if (g != curg) {
            if (curg >= 0) {
                atomicAdd(&g_sums[curg * HD + o], rsum);
                if (o == 0) atomicAdd(&g_cnts[curg], rcnt);
            }
            curg = g; rsum = 0.f; rcnt = 0.f;
        }
        rsum += fmaxf(__ldg(agg + (size_t)node * 16 + o), 0.f);
        rcnt += 1.f;
    }
    if (curg >= 0) {
        atomicAdd(&g_sums[curg * HD + o], rsum);
        if (o == 0) atomicAdd(&g_cnts[curg], rcnt);
    }
}

__global__ void final_kernel(float* __restrict__ out)
{
    int t = threadIdx.x;
    if (t < NG * HD) {
        float c = g_cnts[t >> 4];
        out[t] = g_sums[t] / fmaxf(c, 1.f);
    }
}

// ---------------------------------------------------------------------------
// Launch
// ---------------------------------------------------------------------------
extern "C" void kernel_launch(void* const* d_in, const int* in_sizes, int n_in,
                              void* d_out, int out_size)
{
    const float* x     = (const float*)d_in[0];
    const float* ea    = (const float*)d_in[1];
    const float* W1    = (const float*)d_in[2];
    const float* b1    = (const float*)d_in[3];
    const float* root1 = (const float*)d_in[4];
    const float* bias1 = (const float*)d_in[5];
    const float* W2    = (const float*)d_in[6];
    const float* b2    = (const float*)d_in[7];
    const float* root2 = (const float*)d_in[8];
    const float* bias2 = (const float*)d_in[9];
    const int*   ei    = (const int*)d_in[10];
    const int*   batch = (const int*)d_in[11];
    float* out = (float*)d_out;

    __half* v;
    float *bb, *agg1, *agg2;
    cudaGetSymbolAddress((void**)&v, g_v);
    cudaGetSymbolAddress((void**)&bb, g_bb);
    cudaGetSymbolAddress((void**)&agg1, g_agg1);
    cudaGetSymbolAddress((void**)&agg2, g_agg2);

    const int prep_grid = (NN + 63) / 64;
    const int edge_grid = (EE * 8 + 255) / 256;
    const int pool_halves = (NN + POOL_NODES_PER_HALF - 1) / POOL_NODES_PER_HALF;
    const int pool_grid = (pool_halves / 2 + 7) / 8 + 1;

    prep_kernel<false, true><<<prep_grid, 256>>>(x, W1, b1, root1, bias1, v, bb, agg1);
    edge_kernel<<<edge_grid, 256>>>(ei, ea, v, bb, agg1);
    prep_kernel<true, false><<<prep_grid, 256>>>(agg1, W2, b2, root2, bias2, v, bb, agg2);
    edge_kernel<<<edge_grid, 256>>>(ei, ea, v, bb, agg2);
    pool_kernel<<<pool_grid, 256>>>(agg2, batch);
    final_kernel<<<1, 512>>>(out);
}

// round 11
// speedup vs baseline: 1.1986x; 1.0020x over previous
#include <cuda_runtime.h>
#include <cuda_fp16.h>

#define NN 100000   // nodes
#define EE 500000   // edges
#define ND 16       // node_dim
#define ED 8        // edge_dim
#define HD 16       // hidden_dim
#define NG 32       // graphs

// Scratch (no allocation allowed -> __device__ globals)
// v layout (fp16, 256B/node): uint4 index node*16 + p*8 + r, p=d>>2, r=o>>1;
// within the 16B: halfs [o_even d0..d3 | o_odd d0..d3] for p=0 (d4..d7 for p=1)
__device__ __align__(128) __half g_v[(size_t)NN * HD * ED];
__device__ __align__(128) float g_bb[(size_t)NN * HD];
__device__ __align__(128) float g_agg1[(size_t)NN * HD];
__device__ __align__(128) float g_agg2[(size_t)NN * HD];
__device__ float g_sums[NG * HD];
__device__ float g_cnts[NG];

// ---- packed f32x2 helpers (Blackwell; ptxas won't auto-fuse, must be PTX) ----
__device__ __forceinline__ unsigned long long pack2(float lo, float hi) {
    unsigned long long r;
    asm("mov.b64 %0, {%1, %2};" : "=l"(r) : "f"(lo), "f"(hi));
    return r;
}
__device__ __forceinline__ void unpack2(unsigned long long v, float& lo, float& hi) {
    asm("mov.b64 {%0, %1}, %2;" : "=f"(lo), "=f"(hi) : "l"(v));
}
__device__ __forceinline__ void fma2(unsigned long long& acc,
                                     unsigned long long a, unsigned long long b) {
    asm("fma.rn.f32x2 %0, %1, %2, %0;" : "+l"(acc) : "l"(a), "l"(b));
}

// ---------------------------------------------------------------------------
// Prep v7: 64 nodes/block, 256 threads. Thread (ng=tid>>4, o=tid&15)
// computes, for 4 nodes n = base+ng*4+j:
//   v[n][o][d] = sum_i h[n][i] * W[d*256 + i*16 + o]   (fp16 packed)
//   bb[n][o]   = sum_i h[n][i] * b[i*16 + o]
//   agg[n][o]  = bias[o] + sum_i h[n][i] * root[i*16 + o]
// Inner loop uses fma.rn.f32x2: 4 packs for the 8 v-accumulators + 1 pack
// for (rt,bb) with coefficient (root,b) staged as float2 in smem.
// W staged transposed as sWt[i][o][d]; h read via LDS.128 (4 i at a time).
// ---------------------------------------------------------------------------
template <bool RELU_IN, bool ZERO_POOL>
__global__ void __launch_bounds__(256) prep_kernel(
    const float* __restrict__ h, const float* __restrict__ W,
    const float* __restrict__ b, const float* __restrict__ root,
    const float* __restrict__ bias,
    __half* __restrict__ v, float* __restrict__ bb, float* __restrict__ agg)
{
    __shared__ __align__(16) float sWt[ND * HD * ED];   // 8 KB, [i][o][d]
    __shared__ __align__(8) float2 sRB[ND * HD];        // (root, b)
    __shared__ float sBias[HD];
    __shared__ __align__(16) float sH[64 * 16];         // 4 KB

    int tid = threadIdx.x;
    if (ZERO_POOL && blockIdx.x == 0) {
        for (int i = tid; i < NG * HD; i += 256) g_sums[i] = 0.f;
        if (tid < NG) g_cnts[tid] = 0.f;
    }
    // transpose W[d][i][o] -> sWt[i][o][d]
    for (int idx = tid; idx < 2048; idx += 256) {
        int d = idx >> 8;
        int io = idx & 255;               // i*16 + o
        sWt[io * 8 + d] = __ldg(W + idx);
    }
    for (int i = tid; i < 256; i += 256)
        sRB[i] = make_float2(__ldg(root + i), __ldg(b + i));
    if (tid < HD) sBias[tid] = bias[tid];

    int nodeBase = blockIdx.x * 64;
    {
        int node = nodeBase + (tid >> 2);
        float4 hv = make_float4(0.f, 0.f, 0.f, 0.f);
        if (node < NN)
            hv = __ldg(reinterpret_cast<const float4*>(h) + (size_t)node * 4 + (tid & 3));
        if (RELU_IN) {
            hv.x = fmaxf(hv.x, 0.f); hv.y = fmaxf(hv.y, 0.f);
            hv.z = fmaxf(hv.z, 0.f); hv.w = fmaxf(hv.w, 0.f);
        }
        reinterpret_cast<float4*>(sH)[tid] = hv;
    }
    __syncthreads();

    int o = tid & 15;
    int ng = tid >> 4;   // 0..15, owns nodes nodeBase + ng*4 + j

    unsigned long long vr2[4][4];   // [j][dpair]: (d0,d1),(d2,d3),(d4,d5),(d6,d7)
    unsigned long long rbacc[4];    // (rt, bb)
    {
        unsigned long long z = pack2(0.f, 0.f);
        unsigned long long bi = pack2(sBias[o], 0.f);
#pragma unroll
        for (int j = 0; j < 4; j++) {
            rbacc[j] = bi;
#pragma unroll
            for (int p = 0; p < 4; p++) vr2[j][p] = z;
        }
    }

    const ulonglong2* wt = reinterpret_cast<const ulonglong2*>(sWt);
    const unsigned long long* rbp = reinterpret_cast<const unsigned long long*>(sRB);

#pragma unroll
    for (int i4 = 0; i4 < 4; i4++) {
        float4 hj[4];
#pragma unroll
        for (int j = 0; j < 4; j++)
            hj[j] = reinterpret_cast<const float4*>(sH + (ng * 4 + j) * 16)[i4];
#pragma unroll
        for (int ii = 0; ii < 4; ii++) {
            int i = i4 * 4 + ii;
            ulonglong2 wlo = wt[(i * 16 + o) * 2];       // (d0,d1),(d2,d3)
            ulonglong2 whi = wt[(i * 16 + o) * 2 + 1];   // (d4,d5),(d6,d7)
            unsigned long long rb = rbp[i * 16 + o];     // (root, b)
#pragma unroll
            for (int j = 0; j < 4; j++) {
                float hv = (ii == 0) ? hj[j].x : (ii == 1) ? hj[j].y
                         : (ii == 2) ? hj[j].z : hj[j].w;
                unsigned long long hv2 = pack2(hv, hv);
                fma2(vr2[j][0], wlo.x, hv2);
                fma2(vr2[j][1], wlo.y, hv2);
                fma2(vr2[j][2], whi.x, hv2);
                fma2(vr2[j][3], whi.y, hv2);
                fma2(rbacc[j], rb, hv2);
            }
        }
    }

    // store: same layout as round 9 (uint2 slot = o, +16 for d4-7)
    uint2* v2 = reinterpret_cast<uint2*>(v);
#pragma unroll
    for (int j = 0; j < 4; j++) {
        int node = nodeBase + ng * 4 + j;
        if (node < NN) {
            float d0, d1, d2, d3, d4, d5, d6, d7;
            unpack2(vr2[j][0], d0, d1);
            unpack2(vr2[j][1], d2, d3);
            unpack2(vr2[j][2], d4, d5);
            unpack2(vr2[j][3], d6, d7);
            union { uint2 u; __half2 h2[2]; } lo, hi;
            lo.h2[0] = __floats2half2_rn(d0, d1);
            lo.h2[1] = __floats2half2_rn(d2, d3);
            hi.h2[0] = __floats2half2_rn(d4, d5);
            hi.h2[1] = __floats2half2_rn(d6, d7);
            size_t base = (size_t)node * 32 + o;
            v2[base] = lo.u;
            v2[base + 16] = hi.u;
            float rtv, bbv;
            unpack2(rbacc[j], rtv, bbv);
            agg[(size_t)node * 16 + o] = rtv;
            bb[(size_t)node * 16 + o] = bbv;
        }
    }
}

// ---------------------------------------------------------------------------
// Edge kernel v6 (unchanged): 8 lanes per edge; lane r owns outputs 2r,2r+1.
// Two LDG.128 at node offsets r*16 and 128+r*16 (fully coalesced). One
// red.global.add.v2.f32 per lane.
// ---------------------------------------------------------------------------
__global__ void __launch_bounds__(256) edge_kernel(
    const int* __restrict__ ei, const float* __restrict__ ea,
    const __half* __restrict__ v, const float* __restrict__ bb,
    float* __restrict__ agg)
{
    int gid = blockIdx.x * 256 + threadIdx.x;
    int e = gid >> 3;
    if (e >= EE) return;
    int r = gid & 7;

    int src = __ldg(ei + e);
    int dst = __ldg(ei + EE + e);

    const float4* eap = reinterpret_cast<const float4*>(ea + (size_t)e * 8);
    float4 ea0 = __ldg(eap);
    float4 ea1 = __ldg(eap + 1);

    const uint4* vb = reinterpret_cast<const uint4*>(v) + (size_t)src * 16;
    union { uint4 u; __half2 h2[4]; } l0, l1;
    l0.u = __ldg(vb + r);
    l1.u = __ldg(vb + 8 + r);

    float2 bb2 = __ldg(reinterpret_cast<const float2*>(bb + (size_t)src * 16) + r);

    float2 a0 = __half22float2(l0.h2[0]);
    float2 a1 = __half22float2(l0.h2[1]);
    float2 a2 = __half22float2(l1.h2[0]);
    float2 a3 = __half22float2(l1.h2[1]);
    float2 b0 = __half22float2(l0.h2[2]);
    float2 b1 = __half22float2(l0.h2[3]);
    float2 b2 = __half22float2(l1.h2[2]);
    float2 b3 = __half22float2(l1.h2[3]);

    float me = bb2.x;
    me = fmaf(ea0.x, a0.x, me); me = fmaf(ea0.y, a0.y, me);
    me = fmaf(ea0.z, a1.x, me); me = fmaf(ea0.w, a1.y, me);
    me = fmaf(ea1.x, a2.x, me); me = fmaf(ea1.y, a2.y, me);
    me = fmaf(ea1.z, a3.x, me); me = fmaf(ea1.w, a3.y, me);

    float mo = bb2.y;
    mo = fmaf(ea0.x, b0.x, mo); mo = fmaf(ea0.y, b0.y, mo);
    mo = fmaf(ea0.z, b1.x, mo); mo = fmaf(ea0.w, b1.y, mo);
    mo = fmaf(ea1.x, b2.x, mo); mo = fmaf(ea1.y, b2.y, mo);
    mo = fmaf(ea1.z, b3.x, mo); mo = fmaf(ea1.w, b3.y, mo);

    asm volatile("red.global.add.v2.f32 [%0], {%1,%2};"
                 :: "l"(agg + (size_t)dst * 16 + r * 2), "f"(me), "f"(mo)
                 : "memory");
}

// ---------------------------------------------------------------------------
// Pooling: batch sorted -> register-accumulate runs, flush on change.
// ---------------------------------------------------------------------------
#define POOL_NODES_PER_HALF 32
__global__ void __launch_bounds__(256) pool_kernel(
    const float* __restrict__ agg, const int* __restrict__ batch)
{
    int gwarp = (blockIdx.x * 256 + threadIdx.x) >> 5;
    int lane = threadIdx.x & 31;
    int o = lane & 15;
    int sub = lane >> 4;
    int base = (gwarp * 2 + sub) * POOL_NODES_PER_HALF;

    float rsum = 0.f, rcnt = 0.f;
    int curg = -1;
#pragma unroll 4
    for (int k = 0; k < POOL_NODES_PER_HALF; k++) {
        int node = base + k;
        if (node >= NN) break;
        int g = __ldg(batch + node);
        if (g != curg) {
            if (curg >= 0) {
                atomicAdd(&g_sums[curg * HD + o], rsum);
                if (o == 0) atomicAdd(&g_cnts[curg], rcnt);
            }
            curg = g; rsum = 0.f; rcnt = 0.f;
        }
        rsum += fmaxf(__ldg(agg + (size_t)node * 16 + o), 0.f);
        rcnt += 1.f;
    }
    if (curg >= 0) {
        atomicAdd(&g_sums[curg * HD + o], rsum);
        if (o == 0) atomicAdd(&g_cnts[curg], rcnt);
    }
}

__global__ void final_kernel(float* __restrict__ out)
{
    int t = threadIdx.x;
    if (t < NG * HD) {
        float c = g_cnts[t >> 4];
        out[t] = g_sums[t] / fmaxf(c, 1.f);
    }
}

// ---------------------------------------------------------------------------
// Launch
// ---------------------------------------------------------------------------
extern "C" void kernel_launch(void* const* d_in, const int* in_sizes, int n_in,
                              void* d_out, int out_size)
{
    const float* x     = (const float*)d_in[0];
    const float* ea    = (const float*)d_in[1];
    const float* W1    = (const float*)d_in[2];
    const float* b1    = (const float*)d_in[3];
    const float* root1 = (const float*)d_in[4];
    const float* bias1 = (const float*)d_in[5];
    const float* W2    = (const float*)d_in[6];
    const float* b2    = (const float*)d_in[7];
    const float* root2 = (const float*)d_in[8];
    const float* bias2 = (const float*)d_in[9];
    const int*   ei    = (const int*)d_in[10];
    const int*   batch = (const int*)d_in[11];
    float* out = (float*)d_out;

    __half* v;
    float *bb, *agg1, *agg2;
    cudaGetSymbolAddress((void**)&v, g_v);
    cudaGetSymbolAddress((void**)&bb, g_bb);
    cudaGetSymbolAddress((void**)&agg1, g_agg1);
    cudaGetSymbolAddress((void**)&agg2, g_agg2);

    const int prep_grid = (NN + 63) / 64;
    const int edge_grid = (EE * 8 + 255) / 256;
    const int pool_halves = (NN + POOL_NODES_PER_HALF - 1) / POOL_NODES_PER_HALF;
    const int pool_grid = (pool_halves / 2 + 7) / 8 + 1;

    prep_kernel<false, true><<<prep_grid, 256>>>(x, W1, b1, root1, bias1, v, bb, agg1);
    edge_kernel<<<edge_grid, 256>>>(ei, ea, v, bb, agg1);
    prep_kernel<true, false><<<prep_grid, 256>>>(agg1, W2, b2, root2, bias2, v, bb, agg2);
    edge_kernel<<<edge_grid, 256>>>(ei, ea, v, bb, agg2);
    pool_kernel<<<pool_grid, 256>>>(agg2, batch);
    final_kernel<<<1, 512>>>(out);
}

// round 12
// speedup vs baseline: 1.4724x; 1.2284x over previous
#include <cuda_runtime.h>
#include <cuda_fp16.h>

#define NN 100000   // nodes
#define EE 500000   // edges
#define ND 16       // node_dim
#define ED 8        // edge_dim
#define HD 16       // hidden_dim
#define NG 32       // graphs

// Scratch (no allocation allowed -> __device__ globals)
// v layout (fp16, 256B/node): uint4 index node*16 + p*8 + r, p=d>>2, r=o>>1;
// within the 16B: halfs [o_even d0..d3 | o_odd d0..d3] for p=0 (d4..d7 for p=1)
__device__ __align__(128) __half g_v[(size_t)NN * HD * ED];
__device__ __align__(128) float g_bb[(size_t)NN * HD];
__device__ __align__(128) float g_agg1[(size_t)NN * HD];
__device__ __align__(128) float g_agg2[(size_t)NN * HD];
__device__ float g_sums[NG * HD];
__device__ float g_cnts[NG];

// ---- packed f32x2 helpers (Blackwell; ptxas won't auto-fuse, must be PTX) ----
__device__ __forceinline__ unsigned long long pack2(float lo, float hi) {
    unsigned long long r;
    asm("mov.b64 %0, {%1, %2};" : "=l"(r) : "f"(lo), "f"(hi));
    return r;
}
__device__ __forceinline__ void unpack2(unsigned long long v, float& lo, float& hi) {
    asm("mov.b64 {%0, %1}, %2;" : "=f"(lo), "=f"(hi) : "l"(v));
}
__device__ __forceinline__ void fma2(unsigned long long& acc,
                                     unsigned long long a, unsigned long long b) {
    asm("fma.rn.f32x2 %0, %1, %2, %0;" : "+l"(acc) : "l"(a), "l"(b));
}

// ---------------------------------------------------------------------------
// Prep v8: 128 threads, 64 nodes/block. Thread (ng=tid>>4 in 0..7, o=tid&15)
// computes 8 nodes (n = base + ng*8 + j, j=0..7):
//   v[n][o][d] = sum_i h[n][i] * W[d*256 + i*16 + o]   (fp16 packed layout)
//   bb[n][o]   = sum_i h[n][i] * b[i*16 + o]
//   agg[n][o]  = bias[o] + sum_i h[n][i] * root[i*16 + o]
// Weights split into sWlo/sWhi float4 arrays (16B stride -> conflict-free
// LDS.128 across the warp); h staged transposed sHt[i][node_local] so the
// inner loop reads 8 h values with 2 broadcast LDS.128.
// ---------------------------------------------------------------------------
template <bool RELU_IN, bool ZERO_POOL>
__global__ void __launch_bounds__(128) prep_kernel(
    const float* __restrict__ h, const float* __restrict__ W,
    const float* __restrict__ b, const float* __restrict__ root,
    const float* __restrict__ bias,
    __half* __restrict__ v, float* __restrict__ bb, float* __restrict__ agg)
{
    __shared__ __align__(16) float4 sWlo[ND * HD];   // 4 KB [i*16+o] = (d0..d3)
    __shared__ __align__(16) float4 sWhi[ND * HD];   // 4 KB (d4..d7)
    __shared__ __align__(8) float2 sRB[ND * HD];     // (root, b)
    __shared__ float sBias[HD];
    __shared__ __align__(16) float sHt[ND * 64];     // 4 KB, [i][node_local]

    int tid = threadIdx.x;
    if (ZERO_POOL && blockIdx.x == 0) {
        for (int i = tid; i < NG * HD; i += 128) g_sums[i] = 0.f;
        if (tid < NG) g_cnts[tid] = 0.f;
    }
    // stage weights: k = i*16+o; lanes consecutive k -> coalesced per d
    for (int k = tid; k < 256; k += 128) {
        float4 lo, hi;
        lo.x = __ldg(W + 0 * 256 + k); lo.y = __ldg(W + 1 * 256 + k);
        lo.z = __ldg(W + 2 * 256 + k); lo.w = __ldg(W + 3 * 256 + k);
        hi.x = __ldg(W + 4 * 256 + k); hi.y = __ldg(W + 5 * 256 + k);
        hi.z = __ldg(W + 6 * 256 + k); hi.w = __ldg(W + 7 * 256 + k);
        sWlo[k] = lo; sWhi[k] = hi;
        sRB[k] = make_float2(__ldg(root + k), __ldg(b + k));
    }
    if (tid < HD) sBias[tid] = bias[tid];

    int nodeBase = blockIdx.x * 64;
    // stage h transposed: 64 nodes x 4 quads = 256 float4 loads
    for (int idx = tid; idx < 256; idx += 128) {
        int nl = idx >> 2, q = idx & 3;
        int node = nodeBase + nl;
        float4 hv = make_float4(0.f, 0.f, 0.f, 0.f);
        if (node < NN)
            hv = __ldg(reinterpret_cast<const float4*>(h) + (size_t)node * 4 + q);
        if (RELU_IN) {
            hv.x = fmaxf(hv.x, 0.f); hv.y = fmaxf(hv.y, 0.f);
            hv.z = fmaxf(hv.z, 0.f); hv.w = fmaxf(hv.w, 0.f);
        }
        sHt[(q * 4 + 0) * 64 + nl] = hv.x;
        sHt[(q * 4 + 1) * 64 + nl] = hv.y;
        sHt[(q * 4 + 2) * 64 + nl] = hv.z;
        sHt[(q * 4 + 3) * 64 + nl] = hv.w;
    }
    __syncthreads();

    int o = tid & 15;
    int ng = tid >> 4;   // 0..7, owns nodes nodeBase + ng*8 + j, j=0..7

    unsigned long long vr2[8][4];   // [j][dpair]
    unsigned long long rbacc[8];    // (rt, bb)
    {
        unsigned long long z = pack2(0.f, 0.f);
        unsigned long long bi = pack2(sBias[o], 0.f);
#pragma unroll
        for (int j = 0; j < 8; j++) {
            rbacc[j] = bi;
#pragma unroll
            for (int p = 0; p < 4; p++) vr2[j][p] = z;
        }
    }

    const ulonglong2* wlo2 = reinterpret_cast<const ulonglong2*>(sWlo);
    const ulonglong2* whi2 = reinterpret_cast<const ulonglong2*>(sWhi);
    const unsigned long long* rbp = reinterpret_cast<const unsigned long long*>(sRB);

#pragma unroll
    for (int i = 0; i < 16; i++) {
        ulonglong2 wl = wlo2[i * 16 + o];    // (d0,d1),(d2,d3) — conflict-free
        ulonglong2 wh = whi2[i * 16 + o];    // (d4,d5),(d6,d7)
        unsigned long long rb = rbp[i * 16 + o];
        const float4* hp = reinterpret_cast<const float4*>(sHt + i * 64 + ng * 8);
        float4 ha = hp[0], hb = hp[1];       // broadcast (2 addrs/warp)
        float hv[8] = {ha.x, ha.y, ha.z, ha.w, hb.x, hb.y, hb.z, hb.w};
#pragma unroll
        for (int j = 0; j < 8; j++) {
            unsigned long long hv2 = pack2(hv[j], hv[j]);
            fma2(vr2[j][0], wl.x, hv2);
            fma2(vr2[j][1], wl.y, hv2);
            fma2(vr2[j][2], wh.x, hv2);
            fma2(vr2[j][3], wh.y, hv2);
            fma2(rbacc[j], rb, hv2);
        }
    }

    uint2* v2 = reinterpret_cast<uint2*>(v);
#pragma unroll
    for (int j = 0; j < 8; j++) {
        int node = nodeBase + ng * 8 + j;
        if (node < NN) {
            float d0, d1, d2, d3, d4, d5, d6, d7;
            unpack2(vr2[j][0], d0, d1);
            unpack2(vr2[j][1], d2, d3);
            unpack2(vr2[j][2], d4, d5);
            unpack2(vr2[j][3], d6, d7);
            union { uint2 u; __half2 h2[2]; } lo, hi;
            lo.h2[0] = __floats2half2_rn(d0, d1);
            lo.h2[1] = __floats2half2_rn(d2, d3);
            hi.h2[0] = __floats2half2_rn(d4, d5);
            hi.h2[1] = __floats2half2_rn(d6, d7);
            size_t base = (size_t)node * 32 + o;
            v2[base] = lo.u;
            v2[base + 16] = hi.u;
            float rtv, bbv;
            unpack2(rbacc[j], rtv, bbv);
            agg[(size_t)node * 16 + o] = rtv;
            bb[(size_t)node * 16 + o] = bbv;
        }
    }
}

// ---------------------------------------------------------------------------
// Edge kernel (unchanged): 8 lanes per edge; lane r owns outputs 2r,2r+1.
// Two LDG.128 at node offsets r*16 and 128+r*16 (fully coalesced). One
// red.global.add.v2.f32 per lane.
// ---------------------------------------------------------------------------
__global__ void __launch_bounds__(256) edge_kernel(
    const int* __restrict__ ei, const float* __restrict__ ea,
    const __half* __restrict__ v, const float* __restrict__ bb,
    float* __restrict__ agg)
{
    int gid = blockIdx.x * 256 + threadIdx.x;
    int e = gid >> 3;
    if (e >= EE) return;
    int r = gid & 7;

    int src = __ldg(ei + e);
    int dst = __ldg(ei + EE + e);

    const float4* eap = reinterpret_cast<const float4*>(ea + (size_t)e * 8);
    float4 ea0 = __ldg(eap);
    float4 ea1 = __ldg(eap + 1);

    const uint4* vb = reinterpret_cast<const uint4*>(v) + (size_t)src * 16;
    union { uint4 u; __half2 h2[4]; } l0, l1;
    l0.u = __ldg(vb + r);
    l1.u = __ldg(vb + 8 + r);

    float2 bb2 = __ldg(reinterpret_cast<const float2*>(bb + (size_t)src * 16) + r);

    float2 a0 = __half22float2(l0.h2[0]);
    float2 a1 = __half22float2(l0.h2[1]);
    float2 a2 = __half22float2(l1.h2[0]);
    float2 a3 = __half22float2(l1.h2[1]);
    float2 b0 = __half22float2(l0.h2[2]);
    float2 b1 = __half22float2(l0.h2[3]);
    float2 b2 = __half22float2(l1.h2[2]);
    float2 b3 = __half22float2(l1.h2[3]);

    float me = bb2.x;
    me = fmaf(ea0.x, a0.x, me); me = fmaf(ea0.y, a0.y, me);
    me = fmaf(ea0.z, a1.x, me); me = fmaf(ea0.w, a1.y, me);
    me = fmaf(ea1.x, a2.x, me); me = fmaf(ea1.y, a2.y, me);
    me = fmaf(ea1.z, a3.x, me); me = fmaf(ea1.w, a3.y, me);

    float mo = bb2.y;
    mo = fmaf(ea0.x, b0.x, mo); mo = fmaf(ea0.y, b0.y, mo);
    mo = fmaf(ea0.z, b1.x, mo); mo = fmaf(ea0.w, b1.y, mo);
    mo = fmaf(ea1.x, b2.x, mo); mo = fmaf(ea1.y, b2.y, mo);
    mo = fmaf(ea1.z, b3.x, mo); mo = fmaf(ea1.w, b3.y, mo);

    asm volatile("red.global.add.v2.f32 [%0], {%1,%2};"
                 :: "l"(agg + (size_t)dst * 16 + r * 2), "f"(me), "f"(mo)
                 : "memory");
}

// ---------------------------------------------------------------------------
// Pooling: batch sorted -> register-accumulate runs, flush on change.
// ---------------------------------------------------------------------------
#define POOL_NODES_PER_HALF 32
__global__ void __launch_bounds__(256) pool_kernel(
    const float* __restrict__ agg, const int* __restrict__ batch)
{
    int gwarp = (blockIdx.x * 256 + threadIdx.x) >> 5;
    int lane = threadIdx.x & 31;
    int o = lane & 15;
    int sub = lane >> 4;
    int base = (gwarp * 2 + sub) * POOL_NODES_PER_HALF;

    float rsum = 0.f, rcnt = 0.f;
    int curg = -1;
#pragma unroll 4
    for (int k = 0; k < POOL_NODES_PER_HALF; k++) {
        int node = base + k;
        if (node >= NN) break;
        int g = __ldg(batch + node);
        if (g != curg) {
            if (curg >= 0) {
                atomicAdd(&g_sums[curg * HD + o], rsum);
                if (o == 0) atomicAdd(&g_cnts[curg], rcnt);
            }
            curg = g; rsum = 0.f; rcnt = 0.f;
        }
        rsum += fmaxf(__ldg(agg + (size_t)node * 16 + o), 0.f);
        rcnt += 1.f;
    }
    if (curg >= 0) {
        atomicAdd(&g_sums[curg * HD + o], rsum);
        if (o == 0) atomicAdd(&g_cnts[curg], rcnt);
    }
}

__global__ void final_kernel(float* __restrict__ out)
{
    int t = threadIdx.x;
    if (t < NG * HD) {
        float c = g_cnts[t >> 4];
        out[t] = g_sums[t] / fmaxf(c, 1.f);
    }
}

// ---------------------------------------------------------------------------
// Launch
// ---------------------------------------------------------------------------
extern "C" void kernel_launch(void* const* d_in, const int* in_sizes, int n_in,
                              void* d_out, int out_size)
{
    const float* x     = (const float*)d_in[0];
    const float* ea    = (const float*)d_in[1];
    const float* W1    = (const float*)d_in[2];
    const float* b1    = (const float*)d_in[3];
    const float* root1 = (const float*)d_in[4];
    const float* bias1 = (const float*)d_in[5];
    const float* W2    = (const float*)d_in[6];
    const float* b2    = (const float*)d_in[7];
    const float* root2 = (const float*)d_in[8];
    const float* bias2 = (const float*)d_in[9];
    const int*   ei    = (const int*)d_in[10];
    const int*   batch = (const int*)d_in[11];
    float* out = (float*)d_out;

    __half* v;
    float *bb, *agg1, *agg2;
    cudaGetSymbolAddress((void**)&v, g_v);
    cudaGetSymbolAddress((void**)&bb, g_bb);
    cudaGetSymbolAddress((void**)&agg1, g_agg1);
    cudaGetSymbolAddress((void**)&agg2, g_agg2);

    const int prep_grid = (NN + 63) / 64;
    const int edge_grid = (EE * 8 + 255) / 256;
    const int pool_halves = (NN + POOL_NODES_PER_HALF - 1) / POOL_NODES_PER_HALF;
    const int pool_grid = (pool_halves / 2 + 7) / 8 + 1;

    prep_kernel<false, true><<<prep_grid, 128>>>(x, W1, b1, root1, bias1, v, bb, agg1);
    edge_kernel<<<edge_grid, 256>>>(ei, ea, v, bb, agg1);
    prep_kernel<true, false><<<prep_grid, 128>>>(agg1, W2, b2, root2, bias2, v, bb, agg2);
    edge_kernel<<<edge_grid, 256>>>(ei, ea, v, bb, agg2);
    pool_kernel<<<pool_grid, 256>>>(agg2, batch);
    final_kernel<<<1, 512>>>(out);
}